// round 3
// baseline (speedup 1.0000x reference)
#include <cuda_runtime.h>
#include <cstdint>

#define FULLMASK 0xffffffffu

constexpr int SEQ = 4096, DIM = 128, BLK = 64;
constexpr int NQB = SEQ / BLK;        // 64 q blocks
constexpr int NSPLIT = 2;
constexpr int NKB = SEQ / BLK;        // 64 key blocks
constexpr int JPER = NKB / NSPLIT;    // 32
constexpr int NTHREADS = 256;
constexpr int TSTR = 132;             // tile stride (floats) for tf32 tiles
constexpr int SC_STR = 68;            // score tile stride (floats)

// smem float offsets
constexpr int QHI_OFF = 0;
constexpr int QLO_OFF = QHI_OFF + BLK * TSTR;   //  8448
constexpr int KHI_OFF = QLO_OFF + BLK * TSTR;   // 16896
constexpr int KLO_OFF = KHI_OFF + BLK * TSTR;   // 25344
constexpr int SC_OFF  = KLO_OFF + BLK * TSTR;   // 33792
constexpr int KSM_OFF = SC_OFF + BLK * SC_STR;  // 38144
constexpr int SMEM_FLOATS = KSM_OFF + BLK;      // 38208
constexpr int SMEM_BYTES = SMEM_FLOATS * 4;     // 152832 B

__device__ float g_partial[NSPLIT * SEQ * DIM];  // 4MB static scratch

__device__ __forceinline__ float warp_sum(float v) {
#pragma unroll
  for (int o = 16; o; o >>= 1) v += __shfl_xor_sync(FULLMASK, v, o);
  return v;
}
__device__ __forceinline__ float warp_max(float v) {
#pragma unroll
  for (int o = 16; o; o >>= 1) v = fmaxf(v, __shfl_xor_sync(FULLMASK, v, o));
  return v;
}

// split fp32 into (hi, lo) tf32 pair; hi/lo carried as f32 with tf32-zeroed tails
__device__ __forceinline__ void tf32_split(float x, float& hi, float& lo) {
  uint32_t hb;
  asm("cvt.rna.tf32.f32 %0, %1;" : "=r"(hb) : "f"(x));
  hi = __uint_as_float(hb);
  float r = x - hi;  // exact
  uint32_t lb;
  asm("cvt.rna.tf32.f32 %0, %1;" : "=r"(lb) : "f"(r));
  lo = __uint_as_float(lb);
}

__device__ __forceinline__ void mma_tf32(float* d, const float* a, const float* b) {
  asm volatile(
      "mma.sync.aligned.m16n8k8.row.col.f32.tf32.tf32.f32 "
      "{%0,%1,%2,%3}, {%4,%5,%6,%7}, {%8,%9}, {%0,%1,%2,%3};"
      : "+f"(d[0]), "+f"(d[1]), "+f"(d[2]), "+f"(d[3])
      : "r"(__float_as_uint(a[0])), "r"(__float_as_uint(a[1])),
        "r"(__float_as_uint(a[2])), "r"(__float_as_uint(a[3])),
        "r"(__float_as_uint(b[0])), "r"(__float_as_uint(b[1])));
}

// fill a 64x128 tile (rows x dim) from gmem into hi/lo tf32 smem tiles
__device__ __forceinline__ void fill_tile(const float* __restrict__ g,
                                          float* hi, float* lo, int tid) {
  const float4* g4 = (const float4*)g;
#pragma unroll
  for (int it = 0; it < (BLK * DIM / 4) / NTHREADS; it++) {
    int idx = tid + it * NTHREADS;
    int row = idx >> 5, c4 = (idx & 31) << 2;
    float4 x = g4[idx];
    float h0, l0, h1, l1, h2, l2, h3, l3;
    tf32_split(x.x, h0, l0);
    tf32_split(x.y, h1, l1);
    tf32_split(x.z, h2, l2);
    tf32_split(x.w, h3, l3);
    int o = row * TSTR + c4;
    *(float4*)(hi + o) = make_float4(h0, h1, h2, h3);
    *(float4*)(lo + o) = make_float4(l0, l1, l2, l3);
  }
}

__global__ void __launch_bounds__(NTHREADS, 1)
eco_attn_mma(const float* __restrict__ q, const float* __restrict__ k,
             const float* __restrict__ v) {
  extern __shared__ float smem[];
  float* qhi = smem + QHI_OFF;
  float* qlo = smem + QLO_OFF;
  float* khi = smem + KHI_OFF;
  float* klo = smem + KLO_OFF;
  float* sc = smem + SC_OFF;
  int* ksm = (int*)(smem + KSM_OFF);

  const int split = blockIdx.x;
  const int qb = blockIdx.y;
  const int tid = threadIdx.x;
  const int lane = tid & 31;
  const int wid = tid >> 5;
  const int gid = lane >> 2;   // mma group id (0..7)
  const int tig = lane & 3;    // thread in group
  const int wm = wid & 3;      // warp M tile (rows 16*wm..)
  const int wn = wid >> 2;     // warp N tile (cols 32*wn..)
  const int ty = tid >> 4;     // PV row group (0..15)
  const int tx = tid & 15;     // PV col group (0..15)

  // ---- Q block -> tf32 hi/lo tiles (once) ----
  fill_tile(q + (size_t)qb * BLK * DIM, qhi, qlo, tid);

  float acc[4][8];
#pragma unroll
  for (int a = 0; a < 4; a++)
#pragma unroll
    for (int b = 0; b < 8; b++) acc[a][b] = 0.f;

  for (int jj = 0; jj < JPER; jj++) {
    const int jb = split * JPER + jj;

    // ---- K block -> tf32 hi/lo tiles ----
    fill_tile(k + (size_t)jb * BLK * DIM, khi, klo, tid);
    __syncthreads();  // K ready; all warps' prior PV done (sc reusable)

    // ---- QK^T via 4-pass tf32 mma: warp covers rows 16wm..+15, cols 32wn..+31 ----
    {
      float d[4][4];
#pragma unroll
      for (int nt = 0; nt < 4; nt++)
#pragma unroll
        for (int i = 0; i < 4; i++) d[nt][i] = 0.f;

      const int arow0 = (16 * wm + gid) * TSTR;
      const int arow1 = (16 * wm + gid + 8) * TSTR;
#pragma unroll 4
      for (int kk = 0; kk < 16; kk++) {
        const int k0 = 8 * kk + tig;
        float ah[4], al[4];
        ah[0] = qhi[arow0 + k0];     al[0] = qlo[arow0 + k0];
        ah[1] = qhi[arow1 + k0];     al[1] = qlo[arow1 + k0];
        ah[2] = qhi[arow0 + k0 + 4]; al[2] = qlo[arow0 + k0 + 4];
        ah[3] = qhi[arow1 + k0 + 4]; al[3] = qlo[arow1 + k0 + 4];
#pragma unroll
        for (int nt = 0; nt < 4; nt++) {
          const int brow = (32 * wn + 8 * nt + gid) * TSTR;
          float bh[2], bl[2];
          bh[0] = khi[brow + k0];     bl[0] = klo[brow + k0];
          bh[1] = khi[brow + k0 + 4]; bl[1] = klo[brow + k0 + 4];
          mma_tf32(d[nt], ah, bh);
          mma_tf32(d[nt], ah, bl);
          mma_tf32(d[nt], al, bh);
          mma_tf32(d[nt], al, bl);
        }
      }
      // write scores
      const int rA = 16 * wm + gid, rB = rA + 8;
      const int cb = 32 * wn + 2 * tig;
#pragma unroll
      for (int nt = 0; nt < 4; nt++) {
        *(float2*)(sc + rA * SC_STR + cb + 8 * nt) = make_float2(d[nt][0], d[nt][1]);
        *(float2*)(sc + rB * SC_STR + cb + 8 * nt) = make_float2(d[nt][2], d[nt][3]);
      }
    }
    __syncthreads();

    // ---- per-row softmax + top-p prefix count (warp wid: rows 8wid..8wid+7) ----
#pragma unroll 1
    for (int rr = 0; rr < 8; rr++) {
      const int r = (wid << 3) + rr;
      float* srow = sc + r * SC_STR;
      float x0 = srow[lane], x1 = srow[lane + 32];
      float m = warp_max(fmaxf(x0, x1));
      float e0 = __expf(x0 - m);
      float e1 = __expf(x1 - m);
      float s = warp_sum(e0 + e1);
      float t = 0.95f * s;

      // fast path: max element is exactly 1.0; K=0 iff !(1 < t)
      if (!(1.0f < t)) {
        srow[lane] = 0.f;
        srow[lane + 32] = 0.f;
        if (lane == 0) ksm[r] = 0;
        continue;
      }

      // extract-max loop: identical FP order to sorted sequential cumsum
      float w0 = e0, w1 = e1;
      float cum = 0.f;
      int K = 0;
      bool stop = false;
#pragma unroll 1
      for (int it = 0; it < 64 && !stop; it++) {
        float mm = warp_max(fmaxf(w0, w1));
        if (mm <= 0.f) break;
        unsigned b0 = __ballot_sync(FULLMASK, w0 == mm);
        unsigned b1 = __ballot_sync(FULLMASK, w1 == mm);
        int cnt = __popc(b0) + __popc(b1);
#pragma unroll 1
        for (int i = 0; i < cnt; i++) {
          cum += mm;
          if (cum < t) K++;
          else { stop = true; break; }
        }
        w0 = (w0 == mm) ? 0.f : w0;
        w1 = (w1 == mm) ? 0.f : w1;
      }

      float den = warp_sum(((lane < K) ? e0 : 0.f) + ((lane + 32 < K) ? e1 : 0.f));
      float inv = 1.f / (den + 1e-8f);
      srow[lane] = (lane < K) ? e0 * inv : 0.f;
      srow[lane + 32] = (lane + 32 < K) ? e1 * inv : 0.f;
      if (lane == 0) ksm[r] = K;
    }
    __syncthreads();

    // ---- PV: rows ty+16rr (rr<4), cols 8tx..8tx+7; V via L1 ----
    int kmax = ksm[ty];
    kmax = max(kmax, ksm[ty + 16]);
    kmax = max(kmax, ksm[ty + 32]);
    kmax = max(kmax, ksm[ty + 48]);
    const float4* vg = (const float4*)(v + (size_t)jb * BLK * DIM);
#pragma unroll 1
    for (int c = 0; c < kmax; c++) {
      float w0 = sc[(ty)*SC_STR + c];
      float w1 = sc[(ty + 16) * SC_STR + c];
      float w2 = sc[(ty + 32) * SC_STR + c];
      float w3 = sc[(ty + 48) * SC_STR + c];
      float4 va = __ldg(vg + c * 32 + (tx << 1));
      float4 vb = __ldg(vg + c * 32 + (tx << 1) + 1);
      float vv[8] = {va.x, va.y, va.z, va.w, vb.x, vb.y, vb.z, vb.w};
      float wv[4] = {w0, w1, w2, w3};
#pragma unroll
      for (int rr = 0; rr < 4; rr++)
#pragma unroll
        for (int cc = 0; cc < 8; cc++) acc[rr][cc] = fmaf(wv[rr], vv[cc], acc[rr][cc]);
    }
    // next iteration's post-fill sync orders PV reads vs sc overwrite
  }

  // ---- write split partials ----
  float* pbase = g_partial + ((size_t)split * SEQ + (size_t)qb * BLK) * DIM;
#pragma unroll
  for (int rr = 0; rr < 4; rr++) {
    int r = ty + 16 * rr;
    float4* dst = (float4*)(pbase + (size_t)r * DIM + (tx << 3));
    dst[0] = make_float4(acc[rr][0], acc[rr][1], acc[rr][2], acc[rr][3]);
    dst[1] = make_float4(acc[rr][4], acc[rr][5], acc[rr][6], acc[rr][7]);
  }
}

__global__ void reduce_partials(float* __restrict__ out) {
  const int idx = blockIdx.x * blockDim.x + threadIdx.x;  // float4 index
  const float4* p = (const float4*)g_partial;
  float4 s = p[idx];
#pragma unroll
  for (int sp = 1; sp < NSPLIT; sp++) {
    float4 t = p[(size_t)sp * (SEQ * DIM / 4) + idx];
    s.x += t.x; s.y += t.y; s.z += t.z; s.w += t.w;
  }
  ((float4*)out)[idx] = s;
}

extern "C" void kernel_launch(void* const* d_in, const int* in_sizes, int n_in,
                              void* d_out, int out_size) {
  const float* q = (const float*)d_in[0];
  const float* k = (const float*)d_in[1];
  const float* v = (const float*)d_in[2];
  float* out = (float*)d_out;

  cudaFuncSetAttribute(eco_attn_mma, cudaFuncAttributeMaxDynamicSharedMemorySize,
                       SMEM_BYTES);
  dim3 grid(NSPLIT, NQB);
  eco_attn_mma<<<grid, NTHREADS, SMEM_BYTES>>>(q, k, v);
  reduce_partials<<<(SEQ * DIM / 4) / 256, 256>>>(out);
}

// round 4
// speedup vs baseline: 1.9620x; 1.9620x over previous
#include <cuda_runtime.h>
#include <cuda_fp16.h>
#include <cstdint>

#define FULLMASK 0xffffffffu

constexpr int SEQ = 4096, DIM = 128, BLK = 64;
constexpr int NQB = SEQ / BLK;        // 64 q blocks
constexpr int NSPLIT = 4;
constexpr int JPER = (SEQ / BLK) / NSPLIT;  // 16 k-tiles per CTA
constexpr int NTHREADS = 256;
constexpr int H2STR = 68;             // half2 stride per row (68*2=136 halfs); 68 % 32 == 4 -> bank = lane
constexpr int SC_STR = 68;            // score tile stride (floats)

// smem byte offsets
constexpr int QHI_OFF = 0;                       // 64 x 68 half2 = 17408 B
constexpr int QLO_OFF = 17408;
constexpr int KHI_OFF = 34816;
constexpr int KLO_OFF = 52224;
constexpr int SC_OFF  = 69632;                   // 64 x 68 f32 = 17408 B
constexpr int KC_OFF  = 87040;                   // 64 ints
constexpr int SMEM_BYTES = 87040 + 256;          // 87296

__device__ float g_partial[NSPLIT * SEQ * DIM];  // 8MB static scratch

__device__ __forceinline__ float warp_sum(float v) {
#pragma unroll
  for (int o = 16; o; o >>= 1) v += __shfl_xor_sync(FULLMASK, v, o);
  return v;
}
__device__ __forceinline__ float warp_max(float v) {
#pragma unroll
  for (int o = 16; o; o >>= 1) v = fmaxf(v, __shfl_xor_sync(FULLMASK, v, o));
  return v;
}

// split (x,y) into hi half2 + lo half2 (exact residual split)
__device__ __forceinline__ void h2split(float x, float y, uint32_t& hi, uint32_t& lo) {
  __half2 h = __floats2half2_rn(x, y);
  float2 hf = __half22float2(h);
  __half2 l = __floats2half2_rn(x - hf.x, y - hf.y);
  hi = *reinterpret_cast<uint32_t*>(&h);
  lo = *reinterpret_cast<uint32_t*>(&l);
}

// fp16 mma m16n8k16 row.col, f32 accum
__device__ __forceinline__ void mma16816(float* d, uint32_t a0, uint32_t a1,
                                         uint32_t a2, uint32_t a3, uint32_t b0,
                                         uint32_t b1) {
  asm volatile(
      "mma.sync.aligned.m16n8k16.row.col.f32.f16.f16.f32 "
      "{%0,%1,%2,%3}, {%4,%5,%6,%7}, {%8,%9}, {%0,%1,%2,%3};"
      : "+f"(d[0]), "+f"(d[1]), "+f"(d[2]), "+f"(d[3])
      : "r"(a0), "r"(a1), "r"(a2), "r"(a3), "r"(b0), "r"(b1));
}

// convert a 64x128 f32 tile to hi/lo half2 smem tiles (stride H2STR half2 per row)
__device__ __forceinline__ void fill_tile_h(const float* __restrict__ g,
                                            uint32_t* hi, uint32_t* lo, int tid) {
  const float4* g4 = (const float4*)g;
#pragma unroll
  for (int it = 0; it < (BLK * DIM / 4) / NTHREADS; it++) {
    int idx = tid + it * NTHREADS;
    int row = idx >> 5, c4 = idx & 31;  // float4 index within row
    float4 x = g4[idx];
    uint32_t h01, l01, h23, l23;
    h2split(x.x, x.y, h01, l01);
    h2split(x.z, x.w, h23, l23);
    int o = row * H2STR + 2 * c4;  // half2 units, even -> 8B aligned
    *reinterpret_cast<uint2*>(hi + o) = make_uint2(h01, h23);
    *reinterpret_cast<uint2*>(lo + o) = make_uint2(l01, l23);
  }
}

__global__ void __launch_bounds__(NTHREADS, 2)
eco_attn_h2(const float* __restrict__ q, const float* __restrict__ k,
            const float* __restrict__ v) {
  extern __shared__ char smem[];
  uint32_t* qhi = (uint32_t*)(smem + QHI_OFF);
  uint32_t* qlo = (uint32_t*)(smem + QLO_OFF);
  uint32_t* khi = (uint32_t*)(smem + KHI_OFF);
  uint32_t* klo = (uint32_t*)(smem + KLO_OFF);
  float* sc = (float*)(smem + SC_OFF);
  int* kcnt = (int*)(smem + KC_OFF);

  const int split = blockIdx.x;
  const int qb = blockIdx.y;
  const int tid = threadIdx.x;
  const int lane = tid & 31;
  const int wid = tid >> 5;
  const int gid = lane >> 2;  // 0..7
  const int tig = lane & 3;   // 0..3
  const int wm = wid & 3;     // m16 block: rows 16*wm..
  const int wn = wid >> 2;    // n32 block: cols 32*wn..
  const int ty = tid >> 4;    // PV row group 0..15
  const int tx = tid & 15;    // PV col group 0..15

  // ---- Q block -> half2 hi/lo tiles (once) ----
  fill_tile_h(q + (size_t)qb * BLK * DIM, qhi, qlo, tid);

  float acc[4][8];
#pragma unroll
  for (int a = 0; a < 4; a++)
#pragma unroll
    for (int b = 0; b < 8; b++) acc[a][b] = 0.f;

  const int arow0 = (16 * wm + gid) * H2STR + tig;
  const int arow1 = arow0 + 8 * H2STR;
  const int brow = (32 * wn + gid) * H2STR + tig;

  for (int jj = 0; jj < JPER; jj++) {
    const int jb = split * JPER + jj;

    // ---- K block -> half2 hi/lo tiles ----
    fill_tile_h(k + (size_t)jb * BLK * DIM, khi, klo, tid);
    __syncthreads();  // K ready; all warps past prior PV (sc writable)

    // ---- QK^T: 4-pass double-half mma; warp covers rows 16wm..+15, cols 32wn..+31
    {
      float d[4][4];
#pragma unroll
      for (int nt = 0; nt < 4; nt++)
#pragma unroll
        for (int i = 0; i < 4; i++) d[nt][i] = 0.f;

#pragma unroll
      for (int kk = 0; kk < 8; kk++) {
        const int ko = 8 * kk;  // half2 offset for this k16 chunk
        uint32_t ah0 = qhi[arow0 + ko], ah1 = qhi[arow1 + ko];
        uint32_t ah2 = qhi[arow0 + ko + 4], ah3 = qhi[arow1 + ko + 4];
        uint32_t al0 = qlo[arow0 + ko], al1 = qlo[arow1 + ko];
        uint32_t al2 = qlo[arow0 + ko + 4], al3 = qlo[arow1 + ko + 4];
#pragma unroll
        for (int nt = 0; nt < 4; nt++) {
          const int bo = brow + nt * 8 * H2STR + ko;
          uint32_t bh0 = khi[bo], bh1 = khi[bo + 4];
          uint32_t bl0 = klo[bo], bl1 = klo[bo + 4];
          mma16816(d[nt], ah0, ah1, ah2, ah3, bh0, bh1);
          mma16816(d[nt], ah0, ah1, ah2, ah3, bl0, bl1);
          mma16816(d[nt], al0, al1, al2, al3, bh0, bh1);
          mma16816(d[nt], al0, al1, al2, al3, bl0, bl1);
        }
      }
      // write scores: rows 16wm+gid(+8), cols 32wn+8nt+2tig
      const int rA = 16 * wm + gid, rB = rA + 8;
      const int cb = 32 * wn + 2 * tig;
#pragma unroll
      for (int nt = 0; nt < 4; nt++) {
        *(float2*)(sc + rA * SC_STR + cb + 8 * nt) = make_float2(d[nt][0], d[nt][1]);
        *(float2*)(sc + rB * SC_STR + cb + 8 * nt) = make_float2(d[nt][2], d[nt][3]);
      }
    }
    __syncthreads();

    // ---- per-row softmax + top-p prefix count (warp wid: rows 8wid..8wid+7) ----
#pragma unroll 1
    for (int rr = 0; rr < 8; rr++) {
      const int r = (wid << 3) + rr;
      float* srow = sc + r * SC_STR;
      float x0 = srow[lane], x1 = srow[lane + 32];
      float m = warp_max(fmaxf(x0, x1));
      float e0 = __expf(x0 - m);
      float e1 = __expf(x1 - m);
      float s = warp_sum(e0 + e1);
      float t = 0.95f * s;

      // fast path: largest sorted element is exactly 1.0 -> K=0 iff !(1 < t)
      if (!(1.0f < t)) {
        srow[lane] = 0.f;
        srow[lane + 32] = 0.f;
        if (lane == 0) kcnt[r] = 0;
        continue;
      }

      // extract-max loop: identical FP order to sorted sequential cumsum
      float w0 = e0, w1 = e1;
      float cum = 0.f;
      int K = 0;
      bool stop = false;
#pragma unroll 1
      for (int it = 0; it < 64 && !stop; it++) {
        float mm = warp_max(fmaxf(w0, w1));
        if (mm <= 0.f) break;
        unsigned b0 = __ballot_sync(FULLMASK, w0 == mm);
        unsigned b1 = __ballot_sync(FULLMASK, w1 == mm);
        int cnt = __popc(b0) + __popc(b1);
#pragma unroll 1
        for (int i = 0; i < cnt; i++) {
          cum += mm;
          if (cum < t) K++;
          else { stop = true; break; }
        }
        w0 = (w0 == mm) ? 0.f : w0;
        w1 = (w1 == mm) ? 0.f : w1;
      }

      // positional mask: denominator = sum of e over FIRST K original columns
      float den = warp_sum(((lane < K) ? e0 : 0.f) + ((lane + 32 < K) ? e1 : 0.f));
      float inv = 1.f / (den + 1e-8f);
      srow[lane] = (lane < K) ? e0 * inv : 0.f;
      srow[lane + 32] = (lane + 32 < K) ? e1 * inv : 0.f;
      if (lane == 0) kcnt[r] = K;
    }
    __syncthreads();

    // ---- PV: rows ty+16rr (rr<4), cols 8tx..8tx+7; V via L1 ----
    int kmax = kcnt[ty];
    kmax = max(kmax, kcnt[ty + 16]);
    kmax = max(kmax, kcnt[ty + 32]);
    kmax = max(kmax, kcnt[ty + 48]);
    const float4* vg = (const float4*)(v + (size_t)jb * BLK * DIM);
#pragma unroll 1
    for (int c = 0; c < kmax; c++) {
      float wv[4];
      wv[0] = sc[(ty)*SC_STR + c];
      wv[1] = sc[(ty + 16) * SC_STR + c];
      wv[2] = sc[(ty + 32) * SC_STR + c];
      wv[3] = sc[(ty + 48) * SC_STR + c];
      float4 va = __ldg(vg + c * 32 + (tx << 1));
      float4 vb = __ldg(vg + c * 32 + (tx << 1) + 1);
      float vv[8] = {va.x, va.y, va.z, va.w, vb.x, vb.y, vb.z, vb.w};
#pragma unroll
      for (int rr = 0; rr < 4; rr++)
#pragma unroll
        for (int cc = 0; cc < 8; cc++) acc[rr][cc] = fmaf(wv[rr], vv[cc], acc[rr][cc]);
    }
    // next iteration's first sync orders PV reads vs sc overwrite
  }

  // ---- write split partials ----
  float* pbase = g_partial + ((size_t)split * SEQ + (size_t)qb * BLK) * DIM;
#pragma unroll
  for (int rr = 0; rr < 4; rr++) {
    int r = ty + 16 * rr;
    float4* dst = (float4*)(pbase + (size_t)r * DIM + (tx << 3));
    dst[0] = make_float4(acc[rr][0], acc[rr][1], acc[rr][2], acc[rr][3]);
    dst[1] = make_float4(acc[rr][4], acc[rr][5], acc[rr][6], acc[rr][7]);
  }
}

__global__ void reduce_partials(float* __restrict__ out) {
  const int idx = blockIdx.x * blockDim.x + threadIdx.x;  // float4 index
  const float4* p = (const float4*)g_partial;
  float4 s = p[idx];
#pragma unroll
  for (int sp = 1; sp < NSPLIT; sp++) {
    float4 t = p[(size_t)sp * (SEQ * DIM / 4) + idx];
    s.x += t.x; s.y += t.y; s.z += t.z; s.w += t.w;
  }
  ((float4*)out)[idx] = s;
}

extern "C" void kernel_launch(void* const* d_in, const int* in_sizes, int n_in,
                              void* d_out, int out_size) {
  const float* q = (const float*)d_in[0];
  const float* k = (const float*)d_in[1];
  const float* v = (const float*)d_in[2];
  float* out = (float*)d_out;

  cudaFuncSetAttribute(eco_attn_h2, cudaFuncAttributeMaxDynamicSharedMemorySize,
                       SMEM_BYTES);
  dim3 grid(NSPLIT, NQB);
  eco_attn_h2<<<grid, NTHREADS, SMEM_BYTES>>>(q, k, v);
  reduce_partials<<<(SEQ * DIM / 4) / 256, 256>>>(out);
}

// round 5
// speedup vs baseline: 2.1643x; 1.1032x over previous
#include <cuda_runtime.h>
#include <cuda_fp16.h>
#include <cstdint>

#define FULLMASK 0xffffffffu

constexpr int SEQ = 4096, DIM = 128, BLK = 64;
constexpr int NQB = SEQ / BLK;
constexpr int NSPLIT = 4;
constexpr int JPER = (SEQ / BLK) / NSPLIT;  // 16
constexpr int NTHREADS = 256;
constexpr int H2STR = 68;   // half2 per row; 68 % 32 == 4 -> fragment LDS conflict-free
constexpr int SC_STR = 68;  // floats per score row

// smem byte offsets
constexpr int QHI_OFF = 0;        // 64*68*4 = 17408 B each
constexpr int QLO_OFF = 17408;
constexpr int KHI_OFF = 34816;
constexpr int KLO_OFF = 52224;
constexpr int SC0_OFF = 69632;    // score buffer 0
constexpr int SC1_OFF = 87040;    // score buffer 1
constexpr int KC_OFF  = 104448;   // 64 ints
constexpr int SMEM_BYTES = 104448 + 512;  // 104960 (x2 CTA = 205KB < 228KB)

__device__ float g_partial[NSPLIT * SEQ * DIM];

__device__ __forceinline__ void h2split(float x, float y, uint32_t& hi, uint32_t& lo) {
  __half2 h = __floats2half2_rn(x, y);
  float2 hf = __half22float2(h);
  __half2 l = __floats2half2_rn(x - hf.x, y - hf.y);
  hi = *reinterpret_cast<uint32_t*>(&h);
  lo = *reinterpret_cast<uint32_t*>(&l);
}

__device__ __forceinline__ void mma16816(float* d, uint32_t a0, uint32_t a1,
                                         uint32_t a2, uint32_t a3, uint32_t b0,
                                         uint32_t b1) {
  asm volatile(
      "mma.sync.aligned.m16n8k16.row.col.f32.f16.f16.f32 "
      "{%0,%1,%2,%3}, {%4,%5,%6,%7}, {%8,%9}, {%0,%1,%2,%3};"
      : "+f"(d[0]), "+f"(d[1]), "+f"(d[2]), "+f"(d[3])
      : "r"(a0), "r"(a1), "r"(a2), "r"(a3), "r"(b0), "r"(b1));
}

// direct fill (prologue): gmem f32 tile -> hi/lo half2 smem
__device__ __forceinline__ void fill_tile_h(const float* __restrict__ g,
                                            uint32_t* hi, uint32_t* lo, int tid) {
  const float4* g4 = (const float4*)g;
#pragma unroll
  for (int it = 0; it < (BLK * DIM / 4) / NTHREADS; it++) {
    int idx = tid + it * NTHREADS;
    int row = idx >> 5, c4 = idx & 31;
    float4 x = g4[idx];
    uint32_t h01, l01, h23, l23;
    h2split(x.x, x.y, h01, l01);
    h2split(x.z, x.w, h23, l23);
    int o = row * H2STR + 2 * c4;
    *reinterpret_cast<uint2*>(hi + o) = make_uint2(h01, h23);
    *reinterpret_cast<uint2*>(lo + o) = make_uint2(l01, l23);
  }
}

__global__ void __launch_bounds__(NTHREADS, 2)
eco_attn_h2(const float* __restrict__ q, const float* __restrict__ k,
            const float* __restrict__ v) {
  extern __shared__ char smem[];
  uint32_t* qhi = (uint32_t*)(smem + QHI_OFF);
  uint32_t* qlo = (uint32_t*)(smem + QLO_OFF);
  uint32_t* khi = (uint32_t*)(smem + KHI_OFF);
  uint32_t* klo = (uint32_t*)(smem + KLO_OFF);
  float* sc0 = (float*)(smem + SC0_OFF);
  float* sc1 = (float*)(smem + SC1_OFF);
  int* kcnt = (int*)(smem + KC_OFF);

  const int split = blockIdx.x;
  const int qb = blockIdx.y;
  const int tid = threadIdx.x;
  const int lane = tid & 31;
  const int wid = tid >> 5;
  const int gid = lane >> 2;
  const int tig = lane & 3;
  const int wm = wid & 3;
  const int wn = wid >> 2;
  const int ty = tid >> 4;
  const int tx = tid & 15;

  // ---- prologue: Q tile + first K tile ----
  fill_tile_h(q + (size_t)qb * BLK * DIM, qhi, qlo, tid);
  fill_tile_h(k + (size_t)(split * JPER) * BLK * DIM, khi, klo, tid);
  __syncthreads();

  float acc[4][8];
#pragma unroll
  for (int a = 0; a < 4; a++)
#pragma unroll
    for (int b = 0; b < 8; b++) acc[a][b] = 0.f;

  const int arow0 = (16 * wm + gid) * H2STR + tig;
  const int arow1 = arow0 + 8 * H2STR;
  const int brow = (32 * wn + gid) * H2STR + tig;

  for (int jj = 0; jj < JPER; jj++) {
    const int jb = split * JPER + jj;
    float* scb = (jj & 1) ? sc1 : sc0;

    // ---- prefetch next K tile into registers (latency hidden behind mma) ----
    float4 pf[8];
    {
      const int jn = (jj + 1 < JPER) ? (jb + 1) : jb;
      const float4* g4 = (const float4*)(k + (size_t)jn * BLK * DIM);
#pragma unroll
      for (int it = 0; it < 8; it++) pf[it] = __ldg(g4 + tid + it * NTHREADS);
    }

    // ---- QK^T: 4-pass double-half mma ----
    {
      float d[4][4];
#pragma unroll
      for (int nt = 0; nt < 4; nt++)
#pragma unroll
        for (int i = 0; i < 4; i++) d[nt][i] = 0.f;

#pragma unroll
      for (int kk = 0; kk < 8; kk++) {
        const int ko = 8 * kk;
        uint32_t ah0 = qhi[arow0 + ko], ah1 = qhi[arow1 + ko];
        uint32_t ah2 = qhi[arow0 + ko + 4], ah3 = qhi[arow1 + ko + 4];
        uint32_t al0 = qlo[arow0 + ko], al1 = qlo[arow1 + ko];
        uint32_t al2 = qlo[arow0 + ko + 4], al3 = qlo[arow1 + ko + 4];
#pragma unroll
        for (int nt = 0; nt < 4; nt++) {
          const int bo = brow + nt * 8 * H2STR + ko;
          uint32_t bh0 = khi[bo], bh1 = khi[bo + 4];
          uint32_t bl0 = klo[bo], bl1 = klo[bo + 4];
          mma16816(d[nt], ah0, ah1, ah2, ah3, bh0, bh1);
          mma16816(d[nt], ah0, ah1, ah2, ah3, bl0, bl1);
          mma16816(d[nt], al0, al1, al2, al3, bh0, bh1);
          mma16816(d[nt], al0, al1, al2, al3, bl0, bl1);
        }
      }
      const int rA = 16 * wm + gid, rB = rA + 8;
      const int cb = 32 * wn + 2 * tig;
#pragma unroll
      for (int nt = 0; nt < 4; nt++) {
        *(float2*)(scb + rA * SC_STR + cb + 8 * nt) = make_float2(d[nt][0], d[nt][1]);
        *(float2*)(scb + rB * SC_STR + cb + 8 * nt) = make_float2(d[nt][2], d[nt][3]);
      }
    }
    __syncthreads();  // scores visible; khi/klo no longer read

    // ---- store prefetched next K tile ----
    if (jj + 1 < JPER) {
#pragma unroll
      for (int it = 0; it < 8; it++) {
        int idx = tid + it * NTHREADS;
        int row = idx >> 5, c4 = idx & 31;
        uint32_t h01, l01, h23, l23;
        h2split(pf[it].x, pf[it].y, h01, l01);
        h2split(pf[it].z, pf[it].w, h23, l23);
        int o = row * H2STR + 2 * c4;
        *reinterpret_cast<uint2*>(khi + o) = make_uint2(h01, h23);
        *reinterpret_cast<uint2*>(klo + o) = make_uint2(l01, l23);
      }
    }

    // ---- softmax: batched 8-row reductions (ILP hides shfl latency) ----
    {
      const int r0 = wid << 3;
      float x0[8], x1[8], mx[8], sm[8];
#pragma unroll
      for (int rr = 0; rr < 8; rr++) {
        x0[rr] = scb[(r0 + rr) * SC_STR + lane];
        x1[rr] = scb[(r0 + rr) * SC_STR + lane + 32];
        mx[rr] = fmaxf(x0[rr], x1[rr]);
      }
#pragma unroll
      for (int o = 16; o; o >>= 1)
#pragma unroll
        for (int rr = 0; rr < 8; rr++)
          mx[rr] = fmaxf(mx[rr], __shfl_xor_sync(FULLMASK, mx[rr], o));
#pragma unroll
      for (int rr = 0; rr < 8; rr++) {
        x0[rr] = __expf(x0[rr] - mx[rr]);
        x1[rr] = __expf(x1[rr] - mx[rr]);
        sm[rr] = x0[rr] + x1[rr];
      }
#pragma unroll
      for (int o = 16; o; o >>= 1)
#pragma unroll
        for (int rr = 0; rr < 8; rr++)
          sm[rr] += __shfl_xor_sync(FULLMASK, sm[rr], o);

#pragma unroll
      for (int rr = 0; rr < 8; rr++) {
        float* srow = scb + (r0 + rr) * SC_STR;
        float t = 0.95f * sm[rr];
        if (!(1.0f < t)) {  // K=0 fast path (max exp is exactly 1)
          srow[lane] = 0.f;
          srow[lane + 32] = 0.f;
          if (lane == 0) kcnt[r0 + rr] = 0;
          continue;
        }
        float e0 = x0[rr], e1 = x1[rr];
        float w0 = e0, w1 = e1;
        float cum = 0.f;
        int K = 0;
        bool stop = false;
#pragma unroll 1
        for (int it = 0; it < 64 && !stop; it++) {
          float mm = fmaxf(w0, w1);
#pragma unroll
          for (int o = 16; o; o >>= 1) mm = fmaxf(mm, __shfl_xor_sync(FULLMASK, mm, o));
          if (mm <= 0.f) break;
          unsigned b0 = __ballot_sync(FULLMASK, w0 == mm);
          unsigned b1 = __ballot_sync(FULLMASK, w1 == mm);
          int cnt = __popc(b0) + __popc(b1);
#pragma unroll 1
          for (int i = 0; i < cnt; i++) {
            cum += mm;  // identical FP order to sorted sequential cumsum
            if (cum < t) K++;
            else { stop = true; break; }
          }
          w0 = (w0 == mm) ? 0.f : w0;
          w1 = (w1 == mm) ? 0.f : w1;
        }
        float den = ((lane < K) ? e0 : 0.f) + ((lane + 32 < K) ? e1 : 0.f);
#pragma unroll
        for (int o = 16; o; o >>= 1) den += __shfl_xor_sync(FULLMASK, den, o);
        float inv = 1.f / (den + 1e-8f);
        srow[lane] = (lane < K) ? e0 * inv : 0.f;
        srow[lane + 32] = (lane + 32 < K) ? e1 * inv : 0.f;
        if (lane == 0) kcnt[r0 + rr] = K;
      }
    }
    __syncthreads();  // probs + kcnt + next K tile visible

    // ---- PV: rows ty+16rr, cols 8tx..8tx+7 ----
    int kmax = kcnt[ty];
    kmax = max(kmax, kcnt[ty + 16]);
    kmax = max(kmax, kcnt[ty + 32]);
    kmax = max(kmax, kcnt[ty + 48]);
    const float4* vg = (const float4*)(v + (size_t)jb * BLK * DIM);
#pragma unroll 1
    for (int c = 0; c < kmax; c++) {
      float wv[4];
      wv[0] = scb[(ty)*SC_STR + c];
      wv[1] = scb[(ty + 16) * SC_STR + c];
      wv[2] = scb[(ty + 32) * SC_STR + c];
      wv[3] = scb[(ty + 48) * SC_STR + c];
      float4 va = __ldg(vg + c * 32 + (tx << 1));
      float4 vb = __ldg(vg + c * 32 + (tx << 1) + 1);
      float vv[8] = {va.x, va.y, va.z, va.w, vb.x, vb.y, vb.z, vb.w};
#pragma unroll
      for (int rr = 0; rr < 4; rr++)
#pragma unroll
        for (int cc = 0; cc < 8; cc++) acc[rr][cc] = fmaf(wv[rr], vv[cc], acc[rr][cc]);
    }
    // PV(jj) overlaps next iter's mma/scores (other sc buffer); kcnt overwrite
    // is fenced by next iter's first __syncthreads.
  }

  float* pbase = g_partial + ((size_t)split * SEQ + (size_t)qb * BLK) * DIM;
#pragma unroll
  for (int rr = 0; rr < 4; rr++) {
    int r = ty + 16 * rr;
    float4* dst = (float4*)(pbase + (size_t)r * DIM + (tx << 3));
    dst[0] = make_float4(acc[rr][0], acc[rr][1], acc[rr][2], acc[rr][3]);
    dst[1] = make_float4(acc[rr][4], acc[rr][5], acc[rr][6], acc[rr][7]);
  }
}

__global__ void reduce_partials(float* __restrict__ out) {
  const int idx = blockIdx.x * blockDim.x + threadIdx.x;
  const float4* p = (const float4*)g_partial;
  float4 s = p[idx];
#pragma unroll
  for (int sp = 1; sp < NSPLIT; sp++) {
    float4 t = p[(size_t)sp * (SEQ * DIM / 4) + idx];
    s.x += t.x; s.y += t.y; s.z += t.z; s.w += t.w;
  }
  ((float4*)out)[idx] = s;
}

extern "C" void kernel_launch(void* const* d_in, const int* in_sizes, int n_in,
                              void* d_out, int out_size) {
  const float* q = (const float*)d_in[0];
  const float* k = (const float*)d_in[1];
  const float* v = (const float*)d_in[2];
  float* out = (float*)d_out;

  cudaFuncSetAttribute(eco_attn_h2, cudaFuncAttributeMaxDynamicSharedMemorySize,
                       SMEM_BYTES);
  dim3 grid(NSPLIT, NQB);
  eco_attn_h2<<<grid, NTHREADS, SMEM_BYTES>>>(q, k, v);
  reduce_partials<<<(SEQ * DIM / 4) / 256, 256>>>(out);
}